// round 2
// baseline (speedup 1.0000x reference)
#include <cuda_runtime.h>

#define MAXROWS 8192
#define CAP     8192     // shared-memory candidate capacity (32 KB)
#define NT      512      // threads per block for K1/K2
#define NLOC    72       // per-thread local candidate buffer

__device__ float g_rowmax[MAXROWS];
__device__ float g_rowloss[MAXROWS];

__device__ __forceinline__ float warpReduceSum(float v) {
#pragma unroll
    for (int o = 16; o; o >>= 1) v += __shfl_down_sync(0xffffffffu, v, o);
    return v;
}

// Valid result in thread 0 only. sbuf must have >= NT/32 floats.
__device__ __forceinline__ float blockReduceSum512(float v, float* sbuf) {
    int tid = threadIdx.x;
    v = warpReduceSum(v);
    if ((tid & 31) == 0) sbuf[tid >> 5] = v;
    __syncthreads();
    if (tid < 32) {
        float x = (tid < NT / 32) ? sbuf[tid] : 0.f;
        x = warpReduceSum(x);
        return x;
    }
    return 0.f;
}

// Robust target load: auto-detect int32 vs int64 storage.
// If int64 (values < 2^31), the high 32-bit word of every entry is 0, so the
// odd 32-bit words of the first 32 entries are all zero. For genuine int32
// class indices the probability of that is ~(1/32000)^32 ~ 0.
__device__ __forceinline__ int load_target(const void* tgt, int row, int n, int d) {
    const int* t32 = (const int*)tgt;
    int lim = (n < 32) ? n : 32;
    bool is64 = true;
    for (int i = 0; i < lim; i++) is64 = is64 && (t32[2 * i + 1] == 0) && (n * 2 <= 2 * n);
    // (the loop above only reads within 2*lim ints = 256 B; safe for either dtype
    //  since even an int32 buffer of n>=64 entries covers it; n is 4096 here)
    long long v;
    if (is64) v = ((const long long*)tgt)[row];
    else      v = (long long)t32[row];
    int t = (int)v;
    if (t < 0 || t >= d) t = 0;   // last-resort OOB guard
    return t;
}

// ---------------- K1: per-row max of scaled logits X = 0.5*input ----------------
__global__ __launch_bounds__(NT) void rowmax_kernel(const float* __restrict__ in, int d) {
    int row = blockIdx.x;
    const float* xr = in + (size_t)row * d;
    int nd4 = ((d & 3) == 0) ? (d >> 2) : 0;
    const float4* p4 = (const float4*)xr;
    float m = -3.4e38f;
    for (int i = threadIdx.x; i < nd4; i += NT) {
        float4 v = p4[i];
        m = fmaxf(fmaxf(m, v.x), fmaxf(v.y, fmaxf(v.z, v.w)));
    }
    for (int i = (nd4 << 2) + threadIdx.x; i < d; i += NT)
        m = fmaxf(m, xr[i]);

    __shared__ float sbuf[NT / 32];
#pragma unroll
    for (int o = 16; o; o >>= 1) m = fmaxf(m, __shfl_down_sync(0xffffffffu, m, o));
    if ((threadIdx.x & 31) == 0) sbuf[threadIdx.x >> 5] = m;
    __syncthreads();
    if (threadIdx.x < 32) {
        float x = (threadIdx.x < NT / 32) ? sbuf[threadIdx.x] : -3.4e38f;
#pragma unroll
        for (int o = 16; o; o >>= 1) x = fmaxf(x, __shfl_down_sync(0xffffffffu, x, o));
        if (threadIdx.x == 0) g_rowmax[row] = 0.5f * x;   // max of X = 0.5 * max(input)
    }
}

// ---------------- K2: compact support, bisect in SMEM, compute row loss ----------------
__global__ __launch_bounds__(NT) void bisect_kernel(const float* __restrict__ in,
                                                    const void* __restrict__ tgt,
                                                    int d, int n) {
    int row = blockIdx.x;
    int tid = threadIdx.x;
    int lane = tid & 31, warp = tid >> 5;
    const float* xr = in + (size_t)row * d;

    float maxX   = g_rowmax[row];
    float tau_lo = maxX - 1.0f;
    float tau_hi = maxX - (float)(1.0 / sqrt((double)d));   // max - (1/d)^(alpha-1)

    __shared__ float cand[CAP];
    __shared__ float sbuf[NT / 32];
    __shared__ int   swarp[NT / 32];
    __shared__ float s_bcast;
    __shared__ float s_flo;
    __shared__ int   s_total;
    __shared__ int   s_ovf;

    if (tid == 0) s_ovf = 0;
    __syncthreads();

    // Pass over the row: f_lo sum + deterministic candidate collection (X > tau_lo)
    float lc[NLOC];
    int   c = 0;
    int   ovf = 0;
    float fl = 0.f;
    int nd4 = ((d & 3) == 0) ? (d >> 2) : 0;
    const float4* p4 = (const float4*)xr;
    for (int i = tid; i < nd4; i += NT) {
        float4 v = p4[i];
        float xs0 = 0.5f * v.x, xs1 = 0.5f * v.y, xs2 = 0.5f * v.z, xs3 = 0.5f * v.w;
        float t;
        t = xs0 - tau_lo; if (t > 0.f) { fl = fmaf(t, t, fl); if (c < NLOC) lc[c++] = xs0; else ovf = 1; }
        t = xs1 - tau_lo; if (t > 0.f) { fl = fmaf(t, t, fl); if (c < NLOC) lc[c++] = xs1; else ovf = 1; }
        t = xs2 - tau_lo; if (t > 0.f) { fl = fmaf(t, t, fl); if (c < NLOC) lc[c++] = xs2; else ovf = 1; }
        t = xs3 - tau_lo; if (t > 0.f) { fl = fmaf(t, t, fl); if (c < NLOC) lc[c++] = xs3; else ovf = 1; }
    }
    for (int i = (nd4 << 2) + tid; i < d; i += NT) {
        float xs = 0.5f * xr[i];
        float t = xs - tau_lo;
        if (t > 0.f) { fl = fmaf(t, t, fl); if (c < NLOC) lc[c++] = xs; else ovf = 1; }
    }
    if (ovf) atomicOr(&s_ovf, 1);

    // Deterministic block exclusive scan of per-thread counts
    int incl = c;
#pragma unroll
    for (int o = 1; o < 32; o <<= 1) {
        int y = __shfl_up_sync(0xffffffffu, incl, o);
        if (lane >= o) incl += y;
    }
    if (lane == 31) swarp[warp] = incl;
    __syncthreads();
    if (warp == 0) {
        int x = (lane < NT / 32) ? swarp[lane] : 0;
        int ix = x;
#pragma unroll
        for (int o = 1; o < 32; o <<= 1) {
            int y = __shfl_up_sync(0xffffffffu, ix, o);
            if (lane >= o) ix += y;
        }
        if (lane < NT / 32) swarp[lane] = ix - x;      // exclusive warp base
        if (lane == NT / 32 - 1) s_total = ix;         // block total
    }
    __syncthreads();

    int  total = s_total;
    bool slow  = (total > CAP) || (s_ovf != 0);
    if (!slow) {
        int base = swarp[warp] + (incl - c);
        for (int k = 0; k < c; k++) cand[base + k] = lc[k];
    }

    // f_lo
    float tot = blockReduceSum512(fl, sbuf);
    if (tid == 0) s_flo = tot - 1.0f;
    __syncthreads();
    float f_lo = s_flo;
    int cnt = slow ? 0 : total;

    // Bisection: 15 iterations, sums only over the support set
    float dm    = tau_hi - tau_lo;
    float tau_m = tau_lo;
#pragma unroll 1
    for (int it = 0; it < 15; it++) {
        dm *= 0.5f;
        tau_m = tau_lo + dm;
        float s = 0.f;
        if (!slow) {
            for (int i = tid; i < cnt; i += NT) {
                float t = fmaxf(cand[i] - tau_m, 0.f);
                s = fmaf(t, t, s);
            }
        } else {
            for (int i = tid; i < d; i += NT) {
                float t = fmaxf(0.5f * __ldg(xr + i) - tau_m, 0.f);
                s = fmaf(t, t, s);
            }
        }
        float fm = blockReduceSum512(s, sbuf);
        if (tid == 0) {
            fm -= 1.0f;
            s_bcast = (fm * f_lo >= 0.f) ? tau_m : tau_lo;
        }
        __syncthreads();
        tau_lo = s_bcast;
    }

    // Final pass at last tau_m: S3 = sum p^1.5 = sum t^3 ; PX = sum p * X
    float s3 = 0.f, px = 0.f;
    if (!slow) {
        for (int i = tid; i < cnt; i += NT) {
            float x = cand[i];
            float t = fmaxf(x - tau_m, 0.f);
            float p = t * t;
            s3 = fmaf(p, t, s3);
            px = fmaf(p, x, px);
        }
    } else {
        for (int i = tid; i < d; i += NT) {
            float x = 0.5f * __ldg(xr + i);
            float t = fmaxf(x - tau_m, 0.f);
            float p = t * t;
            s3 = fmaf(p, t, s3);
            px = fmaf(p, x, px);
        }
    }
    float S3 = blockReduceSum512(s3, sbuf);
    __syncthreads();
    float PX = blockReduceSum512(px, sbuf);
    if (tid == 0) {
        int t = load_target(tgt, row, n, d);
        float xt = __ldg(xr + t);                         // input[row, target]
        // loss = (1 - S3)/(alpha*(alpha-1)) + sum(p*input) - input[target]
        //      = (1 - S3)/0.75 + 2*PX - xt     (input = 2*X)
        float loss = (1.0f - S3) / 0.75f + 2.0f * PX - xt;
        g_rowloss[row] = loss;
    }
}

// ---------------- K3: deterministic mean over rows ----------------
__global__ __launch_bounds__(1024) void reduce_kernel(float* __restrict__ out, int n) {
    __shared__ float sbuf[32];
    float s = 0.f;
    for (int i = threadIdx.x; i < n; i += 1024) s += g_rowloss[i];
    s = warpReduceSum(s);
    if ((threadIdx.x & 31) == 0) sbuf[threadIdx.x >> 5] = s;
    __syncthreads();
    if (threadIdx.x < 32) {
        float x = (threadIdx.x < 32) ? sbuf[threadIdx.x] : 0.f;
        x = warpReduceSum(x);
        if (threadIdx.x == 0) out[0] = x / (float)n;
    }
}

extern "C" void kernel_launch(void* const* d_in, const int* in_sizes, int n_in,
                              void* d_out, int out_size) {
    // Pick logits vs targets by size: the big buffer is the [n, d] logits.
    int idx_in = 0, idx_tg = 1;
    if (n_in >= 2 && in_sizes[1] > in_sizes[0]) { idx_in = 1; idx_tg = 0; }
    const float* in  = (const float*)d_in[idx_in];
    const void*  tgt = d_in[idx_tg];

    int n = in_sizes[idx_tg];
    if (n <= 0) n = 1;
    int d = in_sizes[idx_in] / n;
    if (n > MAXROWS) n = MAXROWS;   // shapes are fixed (4096 x 32000)

    rowmax_kernel<<<n, NT>>>(in, d);
    bisect_kernel<<<n, NT>>>(in, tgt, d, n);
    reduce_kernel<<<1, 1024>>>((float*)d_out, n);
}

// round 3
// speedup vs baseline: 1.2735x; 1.2735x over previous
#include <cuda_runtime.h>

#define MAXROWS 8192
#define NT      256                 // threads per block
#define NW      (NT / 32)           // 8 warps
#define SEG     1024                // candidate slots per warp
#define CAP     (NW * SEG)          // 8192 floats = 32 KB shared

__device__ float g_rowloss[MAXROWS];

__device__ __forceinline__ float warpReduceSum(float v) {
#pragma unroll
    for (int o = 16; o; o >>= 1) v += __shfl_down_sync(0xffffffffu, v, o);
    return v;
}

// Result valid in thread 0 only. sbuf >= NW floats.
__device__ __forceinline__ float blockReduceSum(float v, float* sbuf) {
    int tid = threadIdx.x;
    v = warpReduceSum(v);
    if ((tid & 31) == 0) sbuf[tid >> 5] = v;
    __syncthreads();
    if (tid < 32) {
        float x = (tid < NW) ? sbuf[tid] : 0.f;
        x = warpReduceSum(x);
        return x;
    }
    return 0.f;
}

// Robust target load: auto-detect int32 vs int64 storage (int64 -> odd words zero).
__device__ __forceinline__ int load_target(const void* tgt, int row, int n, int d) {
    const int* t32 = (const int*)tgt;
    int lim = (n < 32) ? n : 32;
    bool is64 = true;
    for (int i = 0; i < lim; i++) is64 = is64 && (t32[2 * i + 1] == 0);
    long long v = is64 ? ((const long long*)tgt)[row] : (long long)t32[row];
    int t = (int)v;
    if (t < 0 || t >= d) t = 0;
    return t;
}

// Fused kernel: single streaming pass with warp-ballot compaction of the
// support set into per-warp shared segments, then bisection + loss in SMEM.
__global__ __launch_bounds__(NT) void tsallis_kernel(const float* __restrict__ in,
                                                     const void* __restrict__ tgt,
                                                     int d, int n) {
    int row  = blockIdx.x;
    int tid  = threadIdx.x;
    int lane = tid & 31, warp = tid >> 5;
    unsigned ltmask = (1u << lane) - 1u;
    const float* xr = in + (size_t)row * d;

    __shared__ float cand[CAP];
    __shared__ float sbuf[NW];
    __shared__ float s_wmax[NW];
    __shared__ int   s_wcnt[NW];
    __shared__ float s_bc0, s_bc1;
    __shared__ int   s_ovf;

    if (tid == 0) s_ovf = 0;
    __syncthreads();

    float* seg = cand + warp * SEG;

    // ---- Phase 1: single streaming pass ----
    // Keep X = 0.5*x whenever X > (warp running max) - 1  (superset of true support).
    float wmax = -3.4e38f;
    int   wcnt = 0;          // uniform across the warp
    int   nf4  = d >> 2;
    bool  generic = (d & 3) != 0;

    if (!generic) {
        const float4* p4 = (const float4*)xr;
        // d = 32000 -> nf4 = 8000 = 256*31 + 64: trailing iterations are whole warps,
        // so __ballot_sync with full mask stays convergent.
        for (int i = tid; i < nf4; i += NT) {
            float4 v = p4[i];
            float a0 = 0.5f * v.x, a1 = 0.5f * v.y, a2 = 0.5f * v.z, a3 = 0.5f * v.w;
            float cm = fmaxf(fmaxf(a0, a1), fmaxf(a2, a3));
#pragma unroll
            for (int o = 16; o; o >>= 1) cm = fmaxf(cm, __shfl_xor_sync(0xffffffffu, cm, o));
            wmax = fmaxf(wmax, cm);
            float th = wmax - 1.0f;

            unsigned m;
            int pos;
            m = __ballot_sync(0xffffffffu, a0 > th);
            pos = wcnt + __popc(m & ltmask);
            if (a0 > th && pos < SEG) seg[pos] = a0;
            wcnt += __popc(m);
            m = __ballot_sync(0xffffffffu, a1 > th);
            pos = wcnt + __popc(m & ltmask);
            if (a1 > th && pos < SEG) seg[pos] = a1;
            wcnt += __popc(m);
            m = __ballot_sync(0xffffffffu, a2 > th);
            pos = wcnt + __popc(m & ltmask);
            if (a2 > th && pos < SEG) seg[pos] = a2;
            wcnt += __popc(m);
            m = __ballot_sync(0xffffffffu, a3 > th);
            pos = wcnt + __popc(m & ltmask);
            if (a3 > th && pos < SEG) seg[pos] = a3;
            wcnt += __popc(m);
        }
    } else {
        // Unusual shape: scalar max only, force slow path.
        float m = -3.4e38f;
        for (int i = tid; i < d; i += NT) m = fmaxf(m, 0.5f * xr[i]);
#pragma unroll
        for (int o = 16; o; o >>= 1) m = fmaxf(m, __shfl_xor_sync(0xffffffffu, m, o));
        wmax = m;
        if (tid == 0) s_ovf = 1;
    }

    if (lane == 0) {
        s_wmax[warp] = wmax;
        s_wcnt[warp] = (wcnt <= SEG) ? wcnt : 0;
        if (wcnt > SEG) atomicOr(&s_ovf, 1);
    }
    __syncthreads();

    // Global row max (in X units) and bounds
    if (tid == 0) {
        float mx = s_wmax[0];
#pragma unroll
        for (int w = 1; w < NW; w++) mx = fmaxf(mx, s_wmax[w]);
        s_bc0 = mx;
    }
    __syncthreads();
    float maxX   = s_bc0;
    float tau_lo = maxX - 1.0f;
    float tau_hi = maxX - (float)(1.0 / sqrt((double)d));   // max - (1/d)^(alpha-1)
    bool  slow   = (s_ovf != 0);
    int   mycnt  = slow ? 0 : s_wcnt[warp];

    // ---- f_lo ----
    float fl = 0.f;
    if (!slow) {
        for (int i = lane; i < mycnt; i += 32) {
            float t = fmaxf(seg[i] - tau_lo, 0.f);
            fl = fmaf(t, t, fl);
        }
    } else {
        for (int i = tid; i < d; i += NT) {
            float t = fmaxf(0.5f * __ldg(xr + i) - tau_lo, 0.f);
            fl = fmaf(t, t, fl);
        }
    }
    float tot = blockReduceSum(fl, sbuf);
    if (tid == 0) s_bc1 = tot - 1.0f;
    __syncthreads();
    float f_lo = s_bc1;

    // ---- 15 bisection iterations over the compacted support ----
    float dm    = tau_hi - tau_lo;
    float tau_m = tau_lo;
#pragma unroll 1
    for (int it = 0; it < 15; it++) {
        dm *= 0.5f;
        tau_m = tau_lo + dm;
        float s = 0.f;
        if (!slow) {
            for (int i = lane; i < mycnt; i += 32) {
                float t = fmaxf(seg[i] - tau_m, 0.f);
                s = fmaf(t, t, s);
            }
        } else {
            for (int i = tid; i < d; i += NT) {
                float t = fmaxf(0.5f * __ldg(xr + i) - tau_m, 0.f);
                s = fmaf(t, t, s);
            }
        }
        float fm = blockReduceSum(s, sbuf);
        if (tid == 0) {
            fm -= 1.0f;
            s_bc0 = (fm * f_lo >= 0.f) ? tau_m : tau_lo;
        }
        __syncthreads();
        tau_lo = s_bc0;
    }

    // ---- Final sums at last tau_m: S3 = sum t^3, PX = sum p*X ----
    float s3 = 0.f, px = 0.f;
    if (!slow) {
        for (int i = lane; i < mycnt; i += 32) {
            float x = seg[i];
            float t = fmaxf(x - tau_m, 0.f);
            float p = t * t;
            s3 = fmaf(p, t, s3);
            px = fmaf(p, x, px);
        }
    } else {
        for (int i = tid; i < d; i += NT) {
            float x = 0.5f * __ldg(xr + i);
            float t = fmaxf(x - tau_m, 0.f);
            float p = t * t;
            s3 = fmaf(p, t, s3);
            px = fmaf(p, x, px);
        }
    }
    float S3 = blockReduceSum(s3, sbuf);
    __syncthreads();
    float PX = blockReduceSum(px, sbuf);
    if (tid == 0) {
        int t = load_target(tgt, row, n, d);
        float xt = __ldg(xr + t);
        // loss = (1 - S3)/(alpha*(alpha-1)) + sum(p*input) - input[target]
        //      = (1 - S3)/0.75 + 2*PX - xt     (input = 2*X)
        g_rowloss[row] = (1.0f - S3) / 0.75f + 2.0f * PX - xt;
    }
}

// Deterministic mean over rows
__global__ __launch_bounds__(1024) void reduce_kernel(float* __restrict__ out, int n) {
    __shared__ float sbuf[32];
    float s = 0.f;
    for (int i = threadIdx.x; i < n; i += 1024) s += g_rowloss[i];
    s = warpReduceSum(s);
    if ((threadIdx.x & 31) == 0) sbuf[threadIdx.x >> 5] = s;
    __syncthreads();
    if (threadIdx.x < 32) {
        float x = (threadIdx.x < 32) ? sbuf[threadIdx.x] : 0.f;
        x = warpReduceSum(x);
        if (threadIdx.x == 0) out[0] = x / (float)n;
    }
}

extern "C" void kernel_launch(void* const* d_in, const int* in_sizes, int n_in,
                              void* d_out, int out_size) {
    // Pick logits vs targets by size: the big buffer is the [n, d] logits.
    int idx_in = 0, idx_tg = 1;
    if (n_in >= 2 && in_sizes[1] > in_sizes[0]) { idx_in = 1; idx_tg = 0; }
    const float* in  = (const float*)d_in[idx_in];
    const void*  tgt = d_in[idx_tg];

    int n = in_sizes[idx_tg];
    if (n <= 0) n = 1;
    int d = in_sizes[idx_in] / n;
    if (n > MAXROWS) n = MAXROWS;   // shapes fixed: 4096 x 32000

    tsallis_kernel<<<n, NT>>>(in, tgt, d, n);
    reduce_kernel<<<1, 1024>>>((float*)d_out, n);
}